// round 10
// baseline (speedup 1.0000x reference)
#include <cuda_runtime.h>

// out[b,c,h,w] = max over 4 directional 3x3 Laplacians (zero-padded).
// out = max(s0,s1,s2,s3) - 2*c  (shared center term -> single FFMA).
// Depth-1 software pipeline (4 rotating windows), RPT=16 -> single wave.
// Halos: ONE merged predicated edge LDG (lane 0 takes x[w0-1], lane 31 takes
// x[w0+4]); interior halo slots filled by warp shuffle ONE ITERATION LATER so
// the shuffle never consumes a fresh load (keeps pipeline distance).

#define W   512
#define H   512
#define RPT 16   // rows per thread

__device__ __forceinline__ void load_row(const float* __restrict__ img,
                                         int h, int w0, int lane, float a[6]) {
    if ((unsigned)h >= (unsigned)H) {
        #pragma unroll
        for (int i = 0; i < 6; i++) a[i] = 0.f;
        return;
    }
    const float* row = img + h * W;
    float4 v = __ldg((const float4*)(row + w0));
    a[1] = v.x; a[2] = v.y; a[3] = v.z; a[4] = v.w;

    // Single merged predicated halo load: lane 0 -> left edge, lane 31 -> right edge.
    float hv = 0.f;
    const bool left  = (lane == 0)  && (w0 > 0);
    const bool right = (lane == 31) && (w0 + 4 < W);
    if (left || right)
        hv = __ldg(row + (left ? (w0 - 1) : (w0 + 4)));
    a[0] = hv;   // meaningful only on lane 0; lanes 1..31 overwritten by shuffle
    a[5] = hv;   // meaningful only on lane 31; lanes 0..30 overwritten by shuffle
}

// Fill interior halo slots from neighbor lanes' registers (values loaded
// one iteration ago -- no fresh-load consumption).
__device__ __forceinline__ void finalize_row(int lane, float a[6]) {
    const float l = __shfl_up_sync(0xffffffffu, a[4], 1);    // lane-1's .w = x[w0-1]
    const float r = __shfl_down_sync(0xffffffffu, a[1], 1);  // lane+1's .x = x[w0+4]
    if (lane != 0)  a[0] = l;
    if (lane != 31) a[5] = r;
}

__global__ __launch_bounds__(128, 13)
void maxlap_kernel(const float* __restrict__ x, float* __restrict__ out) {
    const int img  = blockIdx.y;
    const int h0   = blockIdx.x * RPT;
    const int w0   = threadIdx.x * 4;   // 128 threads cover the full 512 row
    const int lane = threadIdx.x & 31;

    const float* in  = x   + (size_t)img * H * W;
    float*       dst = out + (size_t)img * H * W;

    // Window lifecycle: loaded at iter rr (slot (rr+3)&3), finalized at rr+1,
    // used as b/m/t at rr+1/rr+2/rr+3, reloaded at rr+4.
    float win[4][6];
    load_row(in, h0 - 1, w0, lane, win[0]);
    load_row(in, h0,     w0, lane, win[1]);
    load_row(in, h0 + 1, w0, lane, win[2]);
    finalize_row(lane, win[0]);
    finalize_row(lane, win[1]);

    #pragma unroll
    for (int rr = 0; rr < RPT; rr++) {
        if (rr < RPT - 1)
            load_row(in, h0 + rr + 2, w0, lane, win[(rr + 3) & 3]);  // prefetch

        finalize_row(lane, win[(rr + 2) & 3]);  // b row, loaded last iteration

        const float* t = win[ rr      & 3];
        const float* m = win[(rr + 1) & 3];
        const float* b = win[(rr + 2) & 3];

        float4 o;
        float* op = (float*)&o;
        #pragma unroll
        for (int i = 0; i < 4; i++) {
            const float s0 = m[i]     + m[i + 2];
            const float s1 = t[i + 1] + b[i + 1];
            const float s2 = t[i + 2] + b[i];
            const float s3 = t[i]     + b[i + 2];
            const float ms = fmaxf(fmaxf(s0, s1), fmaxf(s2, s3));
            op[i] = fmaf(-2.f, m[i + 1], ms);
        }
        // Streaming store: keep the L2-resident input from being evicted.
        __stcs((float4*)(dst + (h0 + rr) * W + w0), o);
    }
}

extern "C" void kernel_launch(void* const* d_in, const int* in_sizes, int n_in,
                              void* d_out, int out_size) {
    const float* x = (const float*)d_in[0];
    float* out = (float*)d_out;

    const int n_img = in_sizes[0] / (H * W);  // B*C = 48

    dim3 block(W / 4);               // 128 threads = one full row
    dim3 grid(H / RPT, n_img);       // 32 x 48 = 1536 blocks (single wave)
    maxlap_kernel<<<grid, block>>>(x, out);
}

// round 11
// speedup vs baseline: 1.0239x; 1.0239x over previous
#include <cuda_runtime.h>
#include <cstdint>

// out[b,c,h,w] = max over 4 directional 3x3 Laplacians (zero-padded).
// out = max(s0,s1,s2,s3) - 2*c.
// Input tile (rows h0-1 .. h0+16, contiguous in GMEM) streamed into a 9-row
// SMEM ring via cp.async.bulk (6 chunks x 3 rows, one mbarrier each).
// Compute reads 29-cyc LDS instead of ~250-cyc L2; no halo LDGs, no shuffles.
// RPT=16 -> 1536 blocks, 18KB smem -> 11 blocks/SM -> single wave.

#define W     512
#define H     512
#define RPT   16
#define NCH   6      // chunks per block (3 rows each = 18 input rows)
#define RING  9      // smem ring rows (3 chunks)

__device__ __forceinline__ uint32_t smem_u32(const void* p) {
    uint32_t r;
    asm("{ .reg .u64 t; cvta.to.shared.u64 t, %1; cvt.u32.u64 %0, t; }"
        : "=r"(r) : "l"(p));
    return r;
}
__device__ __forceinline__ void mbar_init1(uint32_t a) {
    asm volatile("mbarrier.init.shared.b64 [%0], 1;" :: "r"(a) : "memory");
}
__device__ __forceinline__ void bulk_load(uint32_t dst, const void* src,
                                          uint32_t bytes, uint32_t mbar) {
    asm volatile("mbarrier.arrive.expect_tx.shared.b64 _, [%0], %1;"
                 :: "r"(mbar), "r"(bytes) : "memory");
    asm volatile("cp.async.bulk.shared::cluster.global.mbarrier::complete_tx::bytes "
                 "[%0], [%1], %2, [%3];"
                 :: "r"(dst), "l"(src), "r"(bytes), "r"(mbar) : "memory");
}
__device__ __forceinline__ void mbar_wait0(uint32_t a) {
    asm volatile(
        "{\n\t.reg .pred P;\n"
        "W_%=:\n\t"
        "mbarrier.try_wait.parity.acquire.cta.shared::cta.b64 P, [%0], 0, 0x989680;\n\t"
        "@!P bra W_%=;\n\t}"
        :: "r"(a) : "memory");
}

// 6-wide window of smem row r: a[1..4] = r[w0..w0+3], halos from same row.
__device__ __forceinline__ void load_win(const float* r, int w0, float a[6]) {
    float4 v = *(const float4*)(r + w0);
    a[1] = v.x; a[2] = v.y; a[3] = v.z; a[4] = v.w;
    a[0] = (w0 > 0)     ? r[w0 - 1] : 0.f;
    a[5] = (w0 + 4 < W) ? r[w0 + 4] : 0.f;
}

__global__ __launch_bounds__(128, 11)
void maxlap_kernel(const float* __restrict__ x, float* __restrict__ out) {
    __shared__ __align__(128) float ring[RING][W];
    __shared__ __align__(8) unsigned long long mbar[NCH];

    const int tid = threadIdx.x;
    const int img = blockIdx.y;
    const int h0  = blockIdx.x * RPT;
    const int w0  = tid * 4;
    const bool firstblk = (blockIdx.x == 0);
    const bool lastblk  = (blockIdx.x == gridDim.x - 1);

    const float* in  = x   + (size_t)img * H * W;
    float*       dst = out + (size_t)img * H * W;

    const uint32_t ring_a = smem_u32(ring);
    const uint32_t mbar_a = smem_u32(mbar);

    if (tid == 0) {
        #pragma unroll
        for (int c = 0; c < NCH; c++) mbar_init1(mbar_a + 8u * c);
    }
    // First block: tile row idx0 (global row -1) is zero padding -> ring row 0.
    if (firstblk) *(float4*)(&ring[0][w0]) = make_float4(0.f, 0.f, 0.f, 0.f);
    __syncthreads();   // mbarrier init + zero row visible

    // Issue chunk c: tile idx rows 3c..3c+2 = global rows h0-1+3c .. +2,
    // clamped to [0,H); destination = ring rows (3c % RING) + skipped.
    auto issue = [&](int c) {
        const int g0 = h0 - 1 + 3 * c;
        const int lo = g0 < 0 ? 0 : g0;
        const int hi = (g0 + 3) > H ? H : (g0 + 3);
        const uint32_t d = ring_a + (uint32_t)(((3 * c) % RING) + (lo - g0)) * (W * 4);
        bulk_load(d, in + (size_t)lo * W, (uint32_t)(hi - lo) * W * 4, mbar_a + 8u * c);
    };

    if (tid == 0) { issue(0); issue(1); issue(2); }

    // Prologue: wait chunk0, read tile idx 0..2 windows into registers.
    mbar_wait0(mbar_a + 0);
    float win[4][6];
    load_win(ring[0], w0, win[0]);
    load_win(ring[1], w0, win[1]);
    load_win(ring[2], w0, win[2]);
    __syncthreads();                 // all warps done reading ring rows 0..2
    if (tid == 0) issue(3);          // reuse ring rows 0..2 for idx 9..11

    #pragma unroll
    for (int rr = 0; rr < RPT; rr++) {
        // Gate the prefetch of tile idx rr+3 on its chunk's arrival.
        if (rr == 0)  mbar_wait0(mbar_a + 8u * 1);
        if (rr == 3)  mbar_wait0(mbar_a + 8u * 2);
        if (rr == 6)  mbar_wait0(mbar_a + 8u * 3);
        if (rr == 9)  mbar_wait0(mbar_a + 8u * 4);
        if (rr == 12) mbar_wait0(mbar_a + 8u * 5);

        if (rr < RPT - 1)
            load_win(ring[(rr + 3) % RING], w0, win[(rr + 3) & 3]);  // prefetch

        const float* t = win[ rr      & 3];
        const float* m = win[(rr + 1) & 3];
        const float* b = win[(rr + 2) & 3];

        float4 o;
        float* op = (float*)&o;
        #pragma unroll
        for (int i = 0; i < 4; i++) {
            const float s0 = m[i]     + m[i + 2];
            const float s1 = t[i + 1] + b[i + 1];
            const float s2 = t[i + 2] + b[i];
            const float s3 = t[i]     + b[i + 2];
            const float ms = fmaxf(fmaxf(s0, s1), fmaxf(s2, s3));
            op[i] = fmaf(-2.f, m[i + 1], ms);
        }
        __stcs((float4*)(dst + (h0 + rr) * W + w0), o);

        // Recycle ring slots once all warps are done reading them.
        if (rr == 2) { __syncthreads(); if (tid == 0) issue(4); }  // ring 3..5
        if (rr == 5) {
            __syncthreads();
            if (lastblk) {           // tile idx17 (global row 512) = zeros, ring row 8
                *(float4*)(&ring[8][w0]) = make_float4(0.f, 0.f, 0.f, 0.f);
                __syncthreads();
            }
            if (tid == 0) issue(5);  // ring 6..8 (loads only existing rows)
        }
    }
}

extern "C" void kernel_launch(void* const* d_in, const int* in_sizes, int n_in,
                              void* d_out, int out_size) {
    const float* x = (const float*)d_in[0];
    float* out = (float*)d_out;

    const int n_img = in_sizes[0] / (H * W);  // B*C = 48

    dim3 block(W / 4);               // 128 threads = one full row
    dim3 grid(H / RPT, n_img);       // 32 x 48 = 1536 blocks (single wave)
    maxlap_kernel<<<grid, block>>>(x, out);
}